// round 7
// baseline (speedup 1.0000x reference)
#include <cuda_runtime.h>
#include <stdint.h>

// Problem dims
#define B_DIM 4096
#define NG    3000
#define G     30
#define H     6
#define T0    500
#define T1    50
#define N_TERMS 551
#define N_DG  (N_TERMS * G)   // 16530
#define OUT_COLS 3857         // 551 aux + 3306 nn

// ---------------- scratch (device globals; no allocation) ----------------
__device__ float g_dgT[(size_t)N_DG * B_DIM];    // TRANSPOSED: [16530][B]
__device__ float g_z0[T0 * H * B_DIM];           // channel-major [3000][B]
__device__ float g_n0[T0 * H * B_DIM];
__device__ float g_z1[T1 * H * B_DIM];           // [300][B]
__device__ float g_n1[T1 * H * B_DIM];
__device__ float g_z2[H * B_DIM];                // [6][B]
__device__ float g_mean0[T0 * H], g_rstd0[T0 * H];
__device__ float g_mean1[T1 * H], g_rstd1[T1 * H];
__device__ float g_mean2[H],      g_rstd2[H];

// ---------------- helpers ----------------
__device__ __forceinline__ uint32_t f2tf32(float x) {
    uint32_t u;
    asm("cvt.rna.tf32.f32 %0, %1;" : "=r"(u) : "f"(x));
    return u;
}

#define STS4(buf, off, v) do {                           \
    uint32_t* _p = (uint32_t*)(buf) + (off);             \
    _p[0] = f2tf32((v).x); _p[1] = f2tf32((v).y);        \
    _p[2] = f2tf32((v).z); _p[3] = f2tf32((v).w);        \
} while (0)

// =====================================================================
// Kernel 1: big GEMM  dgT[n, b] = cell[b, :] . Wdg_flat[n, :] + bias[n]
// A [4096,3000] row-major, W [16530,3000] row-major (both K-major -> NT gemm)
// 128x128 block tile, BK=16, tf32 mma.sync m16n8k8, double-buffered SMEM.
// GRID SWAP vs round 2: blockIdx.x = m-tile (32), blockIdx.y = n-tile (130)
// -> consecutive CTAs share the same W tile; W streamed from DRAM ONCE,
//    A becomes L2-resident. Output written transposed for coalesced consumers.
// =====================================================================
__global__ __launch_bounds__(256) void gemm_dg_kernel(
    const float* __restrict__ A, const float* __restrict__ W,
    const float* __restrict__ bias)
{
    __shared__ float As[2][128 * 20];   // stride 20 -> conflict-free frag loads
    __shared__ float Bs[2][128 * 20];

    const int tid  = threadIdx.x;
    const int m0   = blockIdx.x * 128;   // SWAPPED: m varies fastest
    const int n0   = blockIdx.y * 128;
    const int lr   = tid >> 2;          // 0..63  (load row)
    const int lc   = (tid & 3) * 4;     // 0,4,8,12 (load col seg)
    const int warp = tid >> 5;
    const int lane = tid & 31;
    const int wm   = warp & 1;          // warp tile 64(M) x 32(N), 2x4 warps
    const int wn   = warp >> 1;
    const int gq   = lane >> 2;         // groupID
    const int t4   = lane & 3;          // threadID_in_group

    const int NTILES = (NG + 15) / 16;  // 188 (last tile masked)
    const float4 z4 = make_float4(0.f, 0.f, 0.f, 0.f);

    const float* pa0 = A + (size_t)(m0 + lr) * NG;
    const float* pa1 = A + (size_t)(m0 + lr + 64) * NG;
    const int nb0 = n0 + lr, nb1 = n0 + lr + 64;
    const float* pb0 = W + (size_t)nb0 * NG;
    const float* pb1 = W + (size_t)nb1 * NG;
    const bool vb0 = nb0 < N_DG, vb1 = nb1 < N_DG;

    float acc[4][4][4];
#pragma unroll
    for (int i = 0; i < 4; i++)
#pragma unroll
        for (int j = 0; j < 4; j++)
#pragma unroll
            for (int k = 0; k < 4; k++) acc[i][j][k] = 0.f;

    float4 ra0, ra1, rb0, rb1;
    // prologue: tile 0 (k always valid: lc <= 12 < 3000)
    ra0 = *(const float4*)(pa0 + lc);
    ra1 = *(const float4*)(pa1 + lc);
    rb0 = vb0 ? *(const float4*)(pb0 + lc) : z4;
    rb1 = vb1 ? *(const float4*)(pb1 + lc) : z4;
    STS4(As[0], lr * 20 + lc, ra0);
    STS4(As[0], (lr + 64) * 20 + lc, ra1);
    STS4(Bs[0], lr * 20 + lc, rb0);
    STS4(Bs[0], (lr + 64) * 20 + lc, rb1);
    __syncthreads();

    for (int kt = 0; kt < NTILES; kt++) {
        const int st = kt & 1;
        if (kt + 1 < NTILES) {
            const int k = (kt + 1) * 16 + lc;
            const bool vk = k < NG;           // NG % 4 == 0 -> whole-float4 valid
            ra0 = vk ? *(const float4*)(pa0 + k) : z4;
            ra1 = vk ? *(const float4*)(pa1 + k) : z4;
            rb0 = (vk && vb0) ? *(const float4*)(pb0 + k) : z4;
            rb1 = (vk && vb1) ? *(const float4*)(pb1 + k) : z4;
        }
        const float* as = As[st];
        const float* bs = Bs[st];
#pragma unroll
        for (int ks = 0; ks < 2; ks++) {
            const int kk = ks * 8;
            uint32_t af[4][4], bf[4][2];
#pragma unroll
            for (int mf = 0; mf < 4; mf++) {
                const int r = wm * 64 + mf * 16 + gq;
                af[mf][0] = __float_as_uint(as[r * 20 + kk + t4]);
                af[mf][1] = __float_as_uint(as[(r + 8) * 20 + kk + t4]);
                af[mf][2] = __float_as_uint(as[r * 20 + kk + t4 + 4]);
                af[mf][3] = __float_as_uint(as[(r + 8) * 20 + kk + t4 + 4]);
            }
#pragma unroll
            for (int nf = 0; nf < 4; nf++) {
                const int c = wn * 32 + nf * 8 + gq;
                bf[nf][0] = __float_as_uint(bs[c * 20 + kk + t4]);
                bf[nf][1] = __float_as_uint(bs[c * 20 + kk + t4 + 4]);
            }
#pragma unroll
            for (int mf = 0; mf < 4; mf++)
#pragma unroll
                for (int nf = 0; nf < 4; nf++)
                    asm volatile(
                        "mma.sync.aligned.m16n8k8.row.col.f32.tf32.tf32.f32 "
                        "{%0,%1,%2,%3}, {%4,%5,%6,%7}, {%8,%9}, {%0,%1,%2,%3};"
                        : "+f"(acc[mf][nf][0]), "+f"(acc[mf][nf][1]),
                          "+f"(acc[mf][nf][2]), "+f"(acc[mf][nf][3])
                        : "r"(af[mf][0]), "r"(af[mf][1]), "r"(af[mf][2]), "r"(af[mf][3]),
                          "r"(bf[nf][0]), "r"(bf[nf][1]));
        }
        if (kt + 1 < NTILES) {
            const int s2 = (kt + 1) & 1;
            STS4(As[s2], lr * 20 + lc, ra0);
            STS4(As[s2], (lr + 64) * 20 + lc, ra1);
            STS4(Bs[s2], lr * 20 + lc, rb0);
            STS4(Bs[s2], (lr + 64) * 20 + lc, rb1);
        }
        __syncthreads();
    }

    // epilogue: add bias, write g_dgT[col][row]
#pragma unroll
    for (int mf = 0; mf < 4; mf++) {
        const int row = m0 + wm * 64 + mf * 16 + gq;
#pragma unroll
        for (int nf = 0; nf < 4; nf++) {
            const int col = n0 + wn * 32 + nf * 8 + t4 * 2;
            if (col < N_DG) {     // col even, N_DG even -> col+1 also valid
                const float bv0 = bias[col], bv1 = bias[col + 1];
                g_dgT[(size_t)col * B_DIM + row]           = acc[mf][nf][0] + bv0;
                g_dgT[(size_t)(col + 1) * B_DIM + row]     = acc[mf][nf][1] + bv1;
                g_dgT[(size_t)col * B_DIM + row + 8]       = acc[mf][nf][2] + bv0;
                g_dgT[(size_t)(col + 1) * B_DIM + row + 8] = acc[mf][nf][3] + bv1;
            }
        }
    }
}

// =====================================================================
// layer 0: z0 = tanh(dg . W0 + b0); coalesced dgT reads; channel-major out
// =====================================================================
__global__ __launch_bounds__(256) void layer0_kernel(const float* __restrict__ W0,
                                                     const float* __restrict__ b0)
{
    const int t = blockIdx.x;
    const int b = blockIdx.y * 256 + threadIdx.x;
    __shared__ float w[H * G];
    __shared__ float bb[H];
    if (threadIdx.x < H * G) w[threadIdx.x] = W0[t * H * G + threadIdx.x];
    if (threadIdx.x < H)     bb[threadIdx.x] = b0[t * H + threadIdx.x];
    __syncthreads();

    float accv[H];
#pragma unroll
    for (int h = 0; h < H; h++) accv[h] = bb[h];
#pragma unroll
    for (int gi = 0; gi < G; gi++) {
        const float v = g_dgT[(size_t)(t * G + gi) * B_DIM + b];
#pragma unroll
        for (int h = 0; h < H; h++) accv[h] += v * w[h * G + gi];
    }
#pragma unroll
    for (int h = 0; h < H; h++)
        g_z0[(size_t)(t * H + h) * B_DIM + b] = tanhf(accv[h]);
}

// =====================================================================
// BatchNorm stats: one block per channel, channel-major input [C][B]
// =====================================================================
__device__ __forceinline__ void bn_stats_body(const float* __restrict__ x,
                                              float* __restrict__ mean,
                                              float* __restrict__ rstd)
{
    const int c = blockIdx.x;
    const float* p = x + (size_t)c * B_DIM;
    float s = 0.f, q = 0.f;
    for (int i = threadIdx.x; i < B_DIM; i += 256) {
        const float v = p[i];
        s += v; q += v * v;
    }
    __shared__ float sh_s[8], sh_q[8];
#pragma unroll
    for (int o = 16; o > 0; o >>= 1) {
        s += __shfl_down_sync(0xffffffffu, s, o);
        q += __shfl_down_sync(0xffffffffu, q, o);
    }
    const int w = threadIdx.x >> 5, l = threadIdx.x & 31;
    if (l == 0) { sh_s[w] = s; sh_q[w] = q; }
    __syncthreads();
    if (threadIdx.x == 0) {
        float S = 0.f, Q = 0.f;
#pragma unroll
        for (int i = 0; i < 8; i++) { S += sh_s[i]; Q += sh_q[i]; }
        const float m = S / (float)B_DIM;
        const float var = Q / (float)B_DIM - m * m;
        mean[c] = m;
        rstd[c] = rsqrtf(var + 1e-5f);
    }
}
__global__ __launch_bounds__(256) void bn_stats0_kernel() { bn_stats_body(g_z0, g_mean0, g_rstd0); }
__global__ __launch_bounds__(256) void bn_stats1_kernel() { bn_stats_body(g_z1, g_mean1, g_rstd1); }
__global__ __launch_bounds__(256) void bn_stats2_kernel() { bn_stats_body(g_z2, g_mean2, g_rstd2); }

// =====================================================================
// apply BN + aux head, layer 0
// =====================================================================
__global__ __launch_bounds__(256) void apply0_kernel(
    const float* __restrict__ gam, const float* __restrict__ bet,
    const float* __restrict__ aw,  const float* __restrict__ ab,
    const float* __restrict__ av,  const float* __restrict__ ac,
    float* __restrict__ out)
{
    const int t = blockIdx.x;
    const int b = blockIdx.y * 256 + threadIdx.x;
    float s = 0.f;
#pragma unroll
    for (int h = 0; h < H; h++) {
        const int c = t * H + h;
        const float z = g_z0[(size_t)c * B_DIM + b];
        const float n = gam[c] * (z - g_mean0[c]) * g_rstd0[c] + bet[c];
        g_n0[(size_t)c * B_DIM + b] = n;
        out[(size_t)b * OUT_COLS + 551 + c] = n;
        s += n * aw[c];
    }
    out[(size_t)b * OUT_COLS + t] = tanhf(s + ab[t]) * av[t] + ac[t];
}

// =====================================================================
// layer 1: in1 = [n0 children (60) | dg_mid (30)]
// =====================================================================
__global__ __launch_bounds__(256) void layer1_kernel(const float* __restrict__ W1,
                                                     const float* __restrict__ b1)
{
    const int t = blockIdx.x;           // 0..49
    const int b = blockIdx.y * 256 + threadIdx.x;
    __shared__ float w[H * 90];
    __shared__ float bb[H];
    for (int i = threadIdx.x; i < H * 90; i += 256) w[i] = W1[t * H * 90 + i];
    if (threadIdx.x < H) bb[threadIdx.x] = b1[t * H + threadIdx.x];
    __syncthreads();

    float accv[H];
#pragma unroll
    for (int h = 0; h < H; h++) accv[h] = bb[h];
#pragma unroll
    for (int j = 0; j < 60; j++) {
        const float v = g_n0[(size_t)(t * 60 + j) * B_DIM + b];
#pragma unroll
        for (int h = 0; h < H; h++) accv[h] += v * w[h * 90 + j];
    }
#pragma unroll
    for (int gi = 0; gi < G; gi++) {
        const float v = g_dgT[(size_t)((T0 + t) * G + gi) * B_DIM + b];
#pragma unroll
        for (int h = 0; h < H; h++) accv[h] += v * w[h * 90 + 60 + gi];
    }
#pragma unroll
    for (int h = 0; h < H; h++)
        g_z1[(size_t)(t * H + h) * B_DIM + b] = tanhf(accv[h]);
}

__global__ __launch_bounds__(256) void apply1_kernel(
    const float* __restrict__ gam, const float* __restrict__ bet,
    const float* __restrict__ aw,  const float* __restrict__ ab,
    const float* __restrict__ av,  const float* __restrict__ ac,
    float* __restrict__ out)
{
    const int t = blockIdx.x;
    const int b = blockIdx.y * 256 + threadIdx.x;
    float s = 0.f;
#pragma unroll
    for (int h = 0; h < H; h++) {
        const int c = t * H + h;
        const float z = g_z1[(size_t)c * B_DIM + b];
        const float n = gam[c] * (z - g_mean1[c]) * g_rstd1[c] + bet[c];
        g_n1[(size_t)c * B_DIM + b] = n;
        out[(size_t)b * OUT_COLS + 551 + 3000 + c] = n;
        s += n * aw[c];
    }
    out[(size_t)b * OUT_COLS + T0 + t] = tanhf(s + ab[t]) * av[t] + ac[t];
}

// =====================================================================
// root: in2 = [n1 flat (300) | dg root (30)]
// =====================================================================
__global__ __launch_bounds__(256) void root_kernel(const float* __restrict__ W2,
                                                   const float* __restrict__ b2)
{
    const int b = blockIdx.x * 256 + threadIdx.x;
    __shared__ float w[H * 330];
    __shared__ float bb[H];
    for (int i = threadIdx.x; i < H * 330; i += 256) w[i] = W2[i];
    if (threadIdx.x < H) bb[threadIdx.x] = b2[threadIdx.x];
    __syncthreads();

    float accv[H];
#pragma unroll
    for (int h = 0; h < H; h++) accv[h] = bb[h];
    for (int c = 0; c < 300; c++) {
        const float v = g_n1[(size_t)c * B_DIM + b];
#pragma unroll
        for (int h = 0; h < H; h++) accv[h] += v * w[h * 330 + c];
    }
#pragma unroll
    for (int gi = 0; gi < G; gi++) {
        const float v = g_dgT[(size_t)(550 * G + gi) * B_DIM + b];   // dg[:, -1]
#pragma unroll
        for (int h = 0; h < H; h++) accv[h] += v * w[h * 330 + 300 + gi];
    }
#pragma unroll
    for (int h = 0; h < H; h++)
        g_z2[(size_t)h * B_DIM + b] = tanhf(accv[h]);
}

__global__ __launch_bounds__(256) void apply2_kernel(
    const float* __restrict__ gam, const float* __restrict__ bet,
    const float* __restrict__ aw,  const float* __restrict__ ab,
    const float* __restrict__ av,  const float* __restrict__ ac,
    float* __restrict__ out)
{
    const int b = blockIdx.x * 256 + threadIdx.x;
    float s = 0.f;
#pragma unroll
    for (int h = 0; h < H; h++) {
        const float z = g_z2[(size_t)h * B_DIM + b];
        const float n = gam[h] * (z - g_mean2[h]) * g_rstd2[h] + bet[h];
        out[(size_t)b * OUT_COLS + 551 + 3300 + h] = n;
        s += n * aw[h];
    }
    out[(size_t)b * OUT_COLS + 550] = tanhf(s + ab[0]) * av[0] + ac[0];
}

// =====================================================================
// launch
// =====================================================================
extern "C" void kernel_launch(void* const* d_in, const int* in_sizes, int n_in,
                              void* d_out, int out_size)
{
    const float* cell = (const float*)d_in[0];
    const float* Wdg  = (const float*)d_in[1];
    const float* bdg  = (const float*)d_in[2];
    const float* W0   = (const float*)d_in[3];
    const float* b0   = (const float*)d_in[4];
    const float* gam0 = (const float*)d_in[5];
    const float* bet0 = (const float*)d_in[6];
    const float* aw0  = (const float*)d_in[7];
    const float* ab0  = (const float*)d_in[8];
    const float* av0  = (const float*)d_in[9];
    const float* ac0  = (const float*)d_in[10];
    const float* W1   = (const float*)d_in[11];
    const float* b1   = (const float*)d_in[12];
    const float* gam1 = (const float*)d_in[13];
    const float* bet1 = (const float*)d_in[14];
    const float* aw1  = (const float*)d_in[15];
    const float* ab1  = (const float*)d_in[16];
    const float* av1  = (const float*)d_in[17];
    const float* ac1  = (const float*)d_in[18];
    const float* W2   = (const float*)d_in[19];
    const float* b2   = (const float*)d_in[20];
    const float* gam2 = (const float*)d_in[21];
    const float* bet2 = (const float*)d_in[22];
    const float* aw2  = (const float*)d_in[23];
    const float* ab2  = (const float*)d_in[24];
    const float* av2  = (const float*)d_in[25];
    const float* ac2  = (const float*)d_in[26];
    float* out = (float*)d_out;

    // SWAPPED grid: x = m-tile (32), y = n-tile (130)
    dim3 gemm_grid(B_DIM / 128, (N_DG + 127) / 128);
    gemm_dg_kernel<<<gemm_grid, 256>>>(cell, Wdg, bdg);

    layer0_kernel<<<dim3(T0, B_DIM / 256), 256>>>(W0, b0);
    bn_stats0_kernel<<<T0 * H, 256>>>();
    apply0_kernel<<<dim3(T0, B_DIM / 256), 256>>>(gam0, bet0, aw0, ab0, av0, ac0, out);

    layer1_kernel<<<dim3(T1, B_DIM / 256), 256>>>(W1, b1);
    bn_stats1_kernel<<<T1 * H, 256>>>();
    apply1_kernel<<<dim3(T1, B_DIM / 256), 256>>>(gam1, bet1, aw1, ab1, av1, ac1, out);

    root_kernel<<<B_DIM / 256, 256>>>(W2, b2);
    bn_stats2_kernel<<<H, 256>>>();
    apply2_kernel<<<B_DIM / 256, 256>>>(gam2, bet2, aw2, ab2, av2, ac2, out);
}

// round 9
// speedup vs baseline: 1.7629x; 1.7629x over previous
#include <cuda_runtime.h>
#include <cuda_fp16.h>
#include <stdint.h>

// Problem dims
#define B_DIM 4096
#define NG    3000
#define G     30
#define H     6
#define T0    500
#define T1    50
#define N_TERMS 551
#define N_DG  (N_TERMS * G)   // 16530
#define OUT_COLS 3857         // 551 aux + 3306 nn

// ---------------- scratch (device globals; no allocation) ----------------
__device__ float g_dgT[(size_t)N_DG * B_DIM];    // TRANSPOSED: [16530][B]
__device__ float g_z0[T0 * H * B_DIM];           // channel-major [3000][B]
__device__ float g_n0[T0 * H * B_DIM];
__device__ float g_z1[T1 * H * B_DIM];           // [300][B]
__device__ float g_n1[T1 * H * B_DIM];
__device__ float g_z2[H * B_DIM];                // [6][B]
__device__ float g_mean0[T0 * H], g_rstd0[T0 * H];
__device__ float g_mean1[T1 * H], g_rstd1[T1 * H];
__device__ float g_mean2[H],      g_rstd2[H];

// ---------------- helpers ----------------
__device__ __forceinline__ uint32_t f2h2(float lo, float hi) {
    __half2 h = __floats2half2_rn(lo, hi);    // lo -> .x (low 16 bits)
    return *reinterpret_cast<uint32_t*>(&h);
}

// =====================================================================
// Kernel 1: big GEMM  dgT[n, b] = cell[b, :] . Wdg_flat[n, :] + bias[n]
// fp16 mma.sync m16n8k16 (fp32 accum). fp16 mantissa == tf32 mantissa.
// CTA 128x128, BK=32, double-buffered SMEM (half2 words, stride 20 ->
// conflict-free fragment loads). Grid: x = n-tile (validated order).
// =====================================================================
__global__ __launch_bounds__(256) void gemm_dg_kernel(
    const float* __restrict__ A, const float* __restrict__ W,
    const float* __restrict__ bias)
{
    __shared__ uint32_t As[2][128 * 20];   // each word = half2 (2 k-values)
    __shared__ uint32_t Bs[2][128 * 20];

    const int tid  = threadIdx.x;
    const int m0   = blockIdx.y * 128;
    const int n0   = blockIdx.x * 128;
    const int lr   = tid >> 3;          // 0..31 (load row base)
    const int lc   = (tid & 7) * 4;     // 0,4,...,28 (k seg of 4 floats)
    const int warp = tid >> 5;
    const int lane = tid & 31;
    const int wm   = warp & 1;          // warp tile 64(M) x 32(N), 2x4 warps
    const int wn   = warp >> 1;
    const int gq   = lane >> 2;         // groupID
    const int t4   = lane & 3;          // threadID_in_group

    const int NTILES = (NG + 31) / 32;  // 94 (last tile masked)
    const float4 z4 = make_float4(0.f, 0.f, 0.f, 0.f);

    const float* pa[4];
    const float* pb[4];
    bool vb[4];
#pragma unroll
    for (int j = 0; j < 4; j++) {
        pa[j] = A + (size_t)(m0 + lr + 32 * j) * NG;
        const int nb = n0 + lr + 32 * j;
        pb[j] = W + (size_t)nb * NG;
        vb[j] = nb < N_DG;
    }

    float acc[4][4][4];
#pragma unroll
    for (int i = 0; i < 4; i++)
#pragma unroll
        for (int j = 0; j < 4; j++)
#pragma unroll
            for (int k = 0; k < 4; k++) acc[i][j][k] = 0.f;

    float4 fa[4], fb[4];

    #define LDG_TILE(kt) do {                                                  \
        const int kg = (kt) * 32 + lc;                                         \
        const bool vk = kg < NG;                                               \
        _Pragma("unroll")                                                      \
        for (int j = 0; j < 4; j++) {                                          \
            fa[j] = vk ? *(const float4*)(pa[j] + kg) : z4;                    \
            fb[j] = (vk && vb[j]) ? *(const float4*)(pb[j] + kg) : z4;         \
        }                                                                      \
    } while (0)

    #define STS_TILE(st) do {                                                  \
        _Pragma("unroll")                                                      \
        for (int j = 0; j < 4; j++) {                                          \
            const int off = (lr + 32 * j) * 20 + (lc >> 1);                    \
            As[st][off]     = f2h2(fa[j].x, fa[j].y);                          \
            As[st][off + 1] = f2h2(fa[j].z, fa[j].w);                          \
            Bs[st][off]     = f2h2(fb[j].x, fb[j].y);                          \
            Bs[st][off + 1] = f2h2(fb[j].z, fb[j].w);                          \
        }                                                                      \
    } while (0)

    LDG_TILE(0);
    STS_TILE(0);
    __syncthreads();

    for (int kt = 0; kt < NTILES; kt++) {
        const int st = kt & 1;
        if (kt + 1 < NTILES) LDG_TILE(kt + 1);

        const uint32_t* as = As[st];
        const uint32_t* bs = Bs[st];
#pragma unroll
        for (int ks = 0; ks < 2; ks++) {            // two k16 steps per BK=32
            const int kk = ks * 8;                  // half2-word offset
            uint32_t af[4][4], bf[4][2];
#pragma unroll
            for (int mf = 0; mf < 4; mf++) {
                const int r = wm * 64 + mf * 16 + gq;
                af[mf][0] = as[r * 20 + kk + t4];
                af[mf][1] = as[(r + 8) * 20 + kk + t4];
                af[mf][2] = as[r * 20 + kk + t4 + 4];
                af[mf][3] = as[(r + 8) * 20 + kk + t4 + 4];
            }
#pragma unroll
            for (int nf = 0; nf < 4; nf++) {
                const int c = wn * 32 + nf * 8 + gq;
                bf[nf][0] = bs[c * 20 + kk + t4];
                bf[nf][1] = bs[c * 20 + kk + t4 + 4];
            }
#pragma unroll
            for (int mf = 0; mf < 4; mf++)
#pragma unroll
                for (int nf = 0; nf < 4; nf++)
                    asm volatile(
                        "mma.sync.aligned.m16n8k16.row.col.f32.f16.f16.f32 "
                        "{%0,%1,%2,%3}, {%4,%5,%6,%7}, {%8,%9}, {%0,%1,%2,%3};"
                        : "+f"(acc[mf][nf][0]), "+f"(acc[mf][nf][1]),
                          "+f"(acc[mf][nf][2]), "+f"(acc[mf][nf][3])
                        : "r"(af[mf][0]), "r"(af[mf][1]), "r"(af[mf][2]), "r"(af[mf][3]),
                          "r"(bf[nf][0]), "r"(bf[nf][1]));
        }
        if (kt + 1 < NTILES) {
            STS_TILE((kt + 1) & 1);
        }
        __syncthreads();
    }
    #undef LDG_TILE
    #undef STS_TILE

    // epilogue: add bias, write g_dgT[col][row] (transposed for consumers)
#pragma unroll
    for (int mf = 0; mf < 4; mf++) {
        const int row = m0 + wm * 64 + mf * 16 + gq;
#pragma unroll
        for (int nf = 0; nf < 4; nf++) {
            const int col = n0 + wn * 32 + nf * 8 + t4 * 2;
            if (col < N_DG) {     // col even, N_DG even -> col+1 also valid
                const float bv0 = bias[col], bv1 = bias[col + 1];
                g_dgT[(size_t)col * B_DIM + row]           = acc[mf][nf][0] + bv0;
                g_dgT[(size_t)(col + 1) * B_DIM + row]     = acc[mf][nf][1] + bv1;
                g_dgT[(size_t)col * B_DIM + row + 8]       = acc[mf][nf][2] + bv0;
                g_dgT[(size_t)(col + 1) * B_DIM + row + 8] = acc[mf][nf][3] + bv1;
            }
        }
    }
}

// =====================================================================
// layer 0: z0 = tanh(dg . W0 + b0); coalesced dgT reads; channel-major out
// =====================================================================
__global__ __launch_bounds__(256) void layer0_kernel(const float* __restrict__ W0,
                                                     const float* __restrict__ b0)
{
    const int t = blockIdx.x;
    const int b = blockIdx.y * 256 + threadIdx.x;
    __shared__ float w[H * G];
    __shared__ float bb[H];
    if (threadIdx.x < H * G) w[threadIdx.x] = W0[t * H * G + threadIdx.x];
    if (threadIdx.x < H)     bb[threadIdx.x] = b0[t * H + threadIdx.x];
    __syncthreads();

    float accv[H];
#pragma unroll
    for (int h = 0; h < H; h++) accv[h] = bb[h];
#pragma unroll
    for (int gi = 0; gi < G; gi++) {
        const float v = g_dgT[(size_t)(t * G + gi) * B_DIM + b];
#pragma unroll
        for (int h = 0; h < H; h++) accv[h] += v * w[h * G + gi];
    }
#pragma unroll
    for (int h = 0; h < H; h++)
        g_z0[(size_t)(t * H + h) * B_DIM + b] = tanhf(accv[h]);
}

// =====================================================================
// BatchNorm stats: one block per channel, channel-major input [C][B]
// =====================================================================
__device__ __forceinline__ void bn_stats_body(const float* __restrict__ x,
                                              float* __restrict__ mean,
                                              float* __restrict__ rstd)
{
    const int c = blockIdx.x;
    const float* p = x + (size_t)c * B_DIM;
    float s = 0.f, q = 0.f;
    for (int i = threadIdx.x; i < B_DIM; i += 256) {
        const float v = p[i];
        s += v; q += v * v;
    }
    __shared__ float sh_s[8], sh_q[8];
#pragma unroll
    for (int o = 16; o > 0; o >>= 1) {
        s += __shfl_down_sync(0xffffffffu, s, o);
        q += __shfl_down_sync(0xffffffffu, q, o);
    }
    const int w = threadIdx.x >> 5, l = threadIdx.x & 31;
    if (l == 0) { sh_s[w] = s; sh_q[w] = q; }
    __syncthreads();
    if (threadIdx.x == 0) {
        float S = 0.f, Q = 0.f;
#pragma unroll
        for (int i = 0; i < 8; i++) { S += sh_s[i]; Q += sh_q[i]; }
        const float m = S / (float)B_DIM;
        const float var = Q / (float)B_DIM - m * m;
        mean[c] = m;
        rstd[c] = rsqrtf(var + 1e-5f);
    }
}
__global__ __launch_bounds__(256) void bn_stats0_kernel() { bn_stats_body(g_z0, g_mean0, g_rstd0); }
__global__ __launch_bounds__(256) void bn_stats1_kernel() { bn_stats_body(g_z1, g_mean1, g_rstd1); }
__global__ __launch_bounds__(256) void bn_stats2_kernel() { bn_stats_body(g_z2, g_mean2, g_rstd2); }

// =====================================================================
// apply BN + aux head, layer 0
// =====================================================================
__global__ __launch_bounds__(256) void apply0_kernel(
    const float* __restrict__ gam, const float* __restrict__ bet,
    const float* __restrict__ aw,  const float* __restrict__ ab,
    const float* __restrict__ av,  const float* __restrict__ ac,
    float* __restrict__ out)
{
    const int t = blockIdx.x;
    const int b = blockIdx.y * 256 + threadIdx.x;
    float s = 0.f;
#pragma unroll
    for (int h = 0; h < H; h++) {
        const int c = t * H + h;
        const float z = g_z0[(size_t)c * B_DIM + b];
        const float n = gam[c] * (z - g_mean0[c]) * g_rstd0[c] + bet[c];
        g_n0[(size_t)c * B_DIM + b] = n;
        out[(size_t)b * OUT_COLS + 551 + c] = n;
        s += n * aw[c];
    }
    out[(size_t)b * OUT_COLS + t] = tanhf(s + ab[t]) * av[t] + ac[t];
}

// =====================================================================
// layer 1: in1 = [n0 children (60) | dg_mid (30)]
// =====================================================================
__global__ __launch_bounds__(256) void layer1_kernel(const float* __restrict__ W1,
                                                     const float* __restrict__ b1)
{
    const int t = blockIdx.x;           // 0..49
    const int b = blockIdx.y * 256 + threadIdx.x;
    __shared__ float w[H * 90];
    __shared__ float bb[H];
    for (int i = threadIdx.x; i < H * 90; i += 256) w[i] = W1[t * H * 90 + i];
    if (threadIdx.x < H) bb[threadIdx.x] = b1[t * H + threadIdx.x];
    __syncthreads();

    float accv[H];
#pragma unroll
    for (int h = 0; h < H; h++) accv[h] = bb[h];
#pragma unroll
    for (int j = 0; j < 60; j++) {
        const float v = g_n0[(size_t)(t * 60 + j) * B_DIM + b];
#pragma unroll
        for (int h = 0; h < H; h++) accv[h] += v * w[h * 90 + j];
    }
#pragma unroll
    for (int gi = 0; gi < G; gi++) {
        const float v = g_dgT[(size_t)((T0 + t) * G + gi) * B_DIM + b];
#pragma unroll
        for (int h = 0; h < H; h++) accv[h] += v * w[h * 90 + 60 + gi];
    }
#pragma unroll
    for (int h = 0; h < H; h++)
        g_z1[(size_t)(t * H + h) * B_DIM + b] = tanhf(accv[h]);
}

__global__ __launch_bounds__(256) void apply1_kernel(
    const float* __restrict__ gam, const float* __restrict__ bet,
    const float* __restrict__ aw,  const float* __restrict__ ab,
    const float* __restrict__ av,  const float* __restrict__ ac,
    float* __restrict__ out)
{
    const int t = blockIdx.x;
    const int b = blockIdx.y * 256 + threadIdx.x;
    float s = 0.f;
#pragma unroll
    for (int h = 0; h < H; h++) {
        const int c = t * H + h;
        const float z = g_z1[(size_t)c * B_DIM + b];
        const float n = gam[c] * (z - g_mean1[c]) * g_rstd1[c] + bet[c];
        g_n1[(size_t)c * B_DIM + b] = n;
        out[(size_t)b * OUT_COLS + 551 + 3000 + c] = n;
        s += n * aw[c];
    }
    out[(size_t)b * OUT_COLS + T0 + t] = tanhf(s + ab[t]) * av[t] + ac[t];
}

// =====================================================================
// root: in2 = [n1 flat (300) | dg root (30)]
// =====================================================================
__global__ __launch_bounds__(256) void root_kernel(const float* __restrict__ W2,
                                                   const float* __restrict__ b2)
{
    const int b = blockIdx.x * 256 + threadIdx.x;
    __shared__ float w[H * 330];
    __shared__ float bb[H];
    for (int i = threadIdx.x; i < H * 330; i += 256) w[i] = W2[i];
    if (threadIdx.x < H) bb[threadIdx.x] = b2[threadIdx.x];
    __syncthreads();

    float accv[H];
#pragma unroll
    for (int h = 0; h < H; h++) accv[h] = bb[h];
    for (int c = 0; c < 300; c++) {
        const float v = g_n1[(size_t)c * B_DIM + b];
#pragma unroll
        for (int h = 0; h < H; h++) accv[h] += v * w[h * 330 + c];
    }
#pragma unroll
    for (int gi = 0; gi < G; gi++) {
        const float v = g_dgT[(size_t)(550 * G + gi) * B_DIM + b];   // dg[:, -1]
#pragma unroll
        for (int h = 0; h < H; h++) accv[h] += v * w[h * 330 + 300 + gi];
    }
#pragma unroll
    for (int h = 0; h < H; h++)
        g_z2[(size_t)h * B_DIM + b] = tanhf(accv[h]);
}

__global__ __launch_bounds__(256) void apply2_kernel(
    const float* __restrict__ gam, const float* __restrict__ bet,
    const float* __restrict__ aw,  const float* __restrict__ ab,
    const float* __restrict__ av,  const float* __restrict__ ac,
    float* __restrict__ out)
{
    const int b = blockIdx.x * 256 + threadIdx.x;
    float s = 0.f;
#pragma unroll
    for (int h = 0; h < H; h++) {
        const float z = g_z2[(size_t)h * B_DIM + b];
        const float n = gam[h] * (z - g_mean2[h]) * g_rstd2[h] + bet[h];
        out[(size_t)b * OUT_COLS + 551 + 3300 + h] = n;
        s += n * aw[h];
    }
    out[(size_t)b * OUT_COLS + 550] = tanhf(s + ab[0]) * av[0] + ac[0];
}

// =====================================================================
// launch
// =====================================================================
extern "C" void kernel_launch(void* const* d_in, const int* in_sizes, int n_in,
                              void* d_out, int out_size)
{
    const float* cell = (const float*)d_in[0];
    const float* Wdg  = (const float*)d_in[1];
    const float* bdg  = (const float*)d_in[2];
    const float* W0   = (const float*)d_in[3];
    const float* b0   = (const float*)d_in[4];
    const float* gam0 = (const float*)d_in[5];
    const float* bet0 = (const float*)d_in[6];
    const float* aw0  = (const float*)d_in[7];
    const float* ab0  = (const float*)d_in[8];
    const float* av0  = (const float*)d_in[9];
    const float* ac0  = (const float*)d_in[10];
    const float* W1   = (const float*)d_in[11];
    const float* b1   = (const float*)d_in[12];
    const float* gam1 = (const float*)d_in[13];
    const float* bet1 = (const float*)d_in[14];
    const float* aw1  = (const float*)d_in[15];
    const float* ab1  = (const float*)d_in[16];
    const float* av1  = (const float*)d_in[17];
    const float* ac1  = (const float*)d_in[18];
    const float* W2   = (const float*)d_in[19];
    const float* b2   = (const float*)d_in[20];
    const float* gam2 = (const float*)d_in[21];
    const float* bet2 = (const float*)d_in[22];
    const float* aw2  = (const float*)d_in[23];
    const float* ab2  = (const float*)d_in[24];
    const float* av2  = (const float*)d_in[25];
    const float* ac2  = (const float*)d_in[26];
    float* out = (float*)d_out;

    // validated grid order: x = n-tile (130), y = m-tile (32)
    dim3 gemm_grid((N_DG + 127) / 128, B_DIM / 128);
    gemm_dg_kernel<<<gemm_grid, 256>>>(cell, Wdg, bdg);

    layer0_kernel<<<dim3(T0, B_DIM / 256), 256>>>(W0, b0);
    bn_stats0_kernel<<<T0 * H, 256>>>();
    apply0_kernel<<<dim3(T0, B_DIM / 256), 256>>>(gam0, bet0, aw0, ab0, av0, ac0, out);

    layer1_kernel<<<dim3(T1, B_DIM / 256), 256>>>(W1, b1);
    bn_stats1_kernel<<<T1 * H, 256>>>();
    apply1_kernel<<<dim3(T1, B_DIM / 256), 256>>>(gam1, bet1, aw1, ab1, av1, ac1, out);

    root_kernel<<<B_DIM / 256, 256>>>(W2, b2);
    bn_stats2_kernel<<<H, 256>>>();
    apply2_kernel<<<B_DIM / 256, 256>>>(gam2, bet2, aw2, ab2, av2, ac2, out);
}

// round 12
// speedup vs baseline: 1.9497x; 1.1059x over previous
#include <cuda_runtime.h>
#include <cuda_fp16.h>
#include <stdint.h>

// Problem dims
#define B_DIM 4096
#define NG    3000
#define G     30
#define H     6
#define T0    500
#define T1    50
#define N_TERMS 551
#define N_DG  (N_TERMS * G)   // 16530
#define OUT_COLS 3857

#define NT 94                 // k-tiles of 32 (ceil(3000/32))

// ---------------- scratch (device globals; no allocation) ----------------
__device__ __half g_Ah[(size_t)B_DIM * NG];      // fp16 cell_features
__device__ __half g_Wh[(size_t)N_DG * NG];       // fp16 Wdg
__device__ float g_dgT[(size_t)N_DG * B_DIM];    // TRANSPOSED: [16530][B]
__device__ float g_z0[T0 * H * B_DIM];
__device__ float g_n0[T0 * H * B_DIM];
__device__ float g_z1[T1 * H * B_DIM];
__device__ float g_n1[T1 * H * B_DIM];
__device__ float g_z2[H * B_DIM];
__device__ float g_mean0[T0 * H], g_rstd0[T0 * H];
__device__ float g_mean1[T1 * H], g_rstd1[T1 * H];
__device__ float g_mean2[H],      g_rstd2[H];

// ---------------- helpers ----------------
__device__ __forceinline__ uint32_t f2h2(float lo, float hi) {
    __half2 h = __floats2half2_rn(lo, hi);
    return *reinterpret_cast<uint32_t*>(&h);
}
__device__ __forceinline__ uint32_t smem_u32(const void* p) {
    uint32_t a;
    asm("{ .reg .u64 t; cvta.to.shared.u64 t, %1; cvt.u32.u64 %0, t; }" : "=r"(a) : "l"(p));
    return a;
}
__device__ __forceinline__ void cp_async16(uint32_t dst, const void* src, int src_size) {
    asm volatile("cp.async.cg.shared.global [%0], [%1], 16, %2;"
                 :: "r"(dst), "l"(src), "r"(src_size) : "memory");
}
__device__ __forceinline__ void cp_commit() {
    asm volatile("cp.async.commit_group;" ::: "memory");
}
__device__ __forceinline__ void cp_wait0() {
    asm volatile("cp.async.wait_group 0;" ::: "memory");
}

// =====================================================================
// fp32 -> fp16 conversion kernel (vectorized, n % 4 == 0)
// =====================================================================
__global__ __launch_bounds__(256) void conv_h_kernel(
    const float* __restrict__ src, __half* __restrict__ dst, size_t n4)
{
    const size_t i = (size_t)blockIdx.x * 256 + threadIdx.x;
    if (i < n4) {
        const float4 v = *(const float4*)(src + i * 4);
        uint2 o;
        o.x = f2h2(v.x, v.y);
        o.y = f2h2(v.z, v.w);
        *(uint2*)(dst + i * 4) = o;
    }
}

// =====================================================================
// GEMM  dgT[n, b] = cell[b, :] . W[n, :] + bias[n]
// fp16 mma.sync m16n8k16, cp.async producer into validated stride-20
// layout (word w of a row = halves 2w, 2w+1). Grid: x=n-tile(130), y=m(32).
// =====================================================================
__global__ __launch_bounds__(256) void gemm_dg_kernel(
    const __half* __restrict__ Ah, const __half* __restrict__ Wh,
    const float* __restrict__ bias)
{
    __shared__ uint32_t As[2][128 * 20];
    __shared__ uint32_t Bs[2][128 * 20];

    const int tid  = threadIdx.x;
    const int m0   = blockIdx.y * 128;
    const int n0   = blockIdx.x * 128;
    const int warp = tid >> 5;
    const int lane = tid & 31;
    const int wm   = warp & 1;          // 2x4 warps, warp tile 64(M) x 32(N)
    const int wn   = warp >> 1;
    const int gq   = lane >> 2;
    const int t4   = lane & 3;

    const uint32_t a_sm = smem_u32(&As[0][0]);
    const uint32_t b_sm = smem_u32(&Bs[0][0]);

    // per-thread cp.async chunks: 2 for A, 2 for B.
    // chunk ch (0..511): row = ch>>2, seg = ch&3 (16B = 8 halves at k seg*8)
    const int ch0 = tid, ch1 = tid + 256;
    const int ar0 = ch0 >> 2, as0 = ch0 & 3;
    const int ar1 = ch1 >> 2, as1 = ch1 & 3;

    #define ISSUE(stg, kt) do {                                                \
        const int k0 = (kt) * 32;                                              \
        {                                                                      \
            const int k = k0 + as0 * 8;                                        \
            const int sz = (k + 8 <= NG) ? 16 : 0;                             \
            cp_async16(a_sm + ((stg) * 128 * 20 + ar0 * 20 + as0 * 4) * 4,     \
                       Ah + (size_t)(m0 + ar0) * NG + (sz ? k : 0), sz);       \
        }                                                                      \
        {                                                                      \
            const int k = k0 + as1 * 8;                                        \
            const int sz = (k + 8 <= NG) ? 16 : 0;                             \
            cp_async16(a_sm + ((stg) * 128 * 20 + ar1 * 20 + as1 * 4) * 4,     \
                       Ah + (size_t)(m0 + ar1) * NG + (sz ? k : 0), sz);       \
        }                                                                      \
        {                                                                      \
            const int k = k0 + as0 * 8;                                        \
            const int n = n0 + ar0;                                            \
            const int sz = (k + 8 <= NG && n < N_DG) ? 16 : 0;                 \
            cp_async16(b_sm + ((stg) * 128 * 20 + ar0 * 20 + as0 * 4) * 4,     \
                       Wh + (sz ? ((size_t)n * NG + k) : 0), sz);              \
        }                                                                      \
        {                                                                      \
            const int k = k0 + as1 * 8;                                        \
            const int n = n0 + ar1;                                            \
            const int sz = (k + 8 <= NG && n < N_DG) ? 16 : 0;                 \
            cp_async16(b_sm + ((stg) * 128 * 20 + ar1 * 20 + as1 * 4) * 4,     \
                       Wh + (sz ? ((size_t)n * NG + k) : 0), sz);              \
        }                                                                      \
    } while (0)

    float acc[4][4][4];
#pragma unroll
    for (int i = 0; i < 4; i++)
#pragma unroll
        for (int j = 0; j < 4; j++)
#pragma unroll
            for (int k = 0; k < 4; k++) acc[i][j][k] = 0.f;

    ISSUE(0, 0);
    cp_commit();
    cp_wait0();
    __syncthreads();

    for (int kt = 0; kt < NT; kt++) {
        const int st = kt & 1;
        if (kt + 1 < NT) {
            ISSUE(st ^ 1, kt + 1);
            cp_commit();
        }
        const uint32_t* as = As[st];
        const uint32_t* bs = Bs[st];
#pragma unroll
        for (int ks = 0; ks < 2; ks++) {
            const int kk = ks * 8;
            uint32_t af[4][4], bf[4][2];
#pragma unroll
            for (int mf = 0; mf < 4; mf++) {
                const int r = wm * 64 + mf * 16 + gq;
                af[mf][0] = as[r * 20 + kk + t4];
                af[mf][1] = as[(r + 8) * 20 + kk + t4];
                af[mf][2] = as[r * 20 + kk + t4 + 4];
                af[mf][3] = as[(r + 8) * 20 + kk + t4 + 4];
            }
#pragma unroll
            for (int nf = 0; nf < 4; nf++) {
                const int c = wn * 32 + nf * 8 + gq;
                bf[nf][0] = bs[c * 20 + kk + t4];
                bf[nf][1] = bs[c * 20 + kk + t4 + 4];
            }
#pragma unroll
            for (int mf = 0; mf < 4; mf++)
#pragma unroll
                for (int nf = 0; nf < 4; nf++)
                    asm volatile(
                        "mma.sync.aligned.m16n8k16.row.col.f32.f16.f16.f32 "
                        "{%0,%1,%2,%3}, {%4,%5,%6,%7}, {%8,%9}, {%0,%1,%2,%3};"
                        : "+f"(acc[mf][nf][0]), "+f"(acc[mf][nf][1]),
                          "+f"(acc[mf][nf][2]), "+f"(acc[mf][nf][3])
                        : "r"(af[mf][0]), "r"(af[mf][1]), "r"(af[mf][2]), "r"(af[mf][3]),
                          "r"(bf[nf][0]), "r"(bf[nf][1]));
        }
        if (kt + 1 < NT) cp_wait0();
        __syncthreads();
    }
    #undef ISSUE

    // epilogue: add bias, write g_dgT[col][row] (transposed for consumers)
#pragma unroll
    for (int mf = 0; mf < 4; mf++) {
        const int row = m0 + wm * 64 + mf * 16 + gq;
#pragma unroll
        for (int nf = 0; nf < 4; nf++) {
            const int col = n0 + wn * 32 + nf * 8 + t4 * 2;
            if (col < N_DG) {
                const float bv0 = bias[col], bv1 = bias[col + 1];
                g_dgT[(size_t)col * B_DIM + row]           = acc[mf][nf][0] + bv0;
                g_dgT[(size_t)(col + 1) * B_DIM + row]     = acc[mf][nf][1] + bv1;
                g_dgT[(size_t)col * B_DIM + row + 8]       = acc[mf][nf][2] + bv0;
                g_dgT[(size_t)(col + 1) * B_DIM + row + 8] = acc[mf][nf][3] + bv1;
            }
        }
    }
}

// ============ validated epilogue kernels (unchanged) ============

__global__ __launch_bounds__(256) void layer0_kernel(const float* __restrict__ W0,
                                                     const float* __restrict__ b0)
{
    const int t = blockIdx.x;
    const int b = blockIdx.y * 256 + threadIdx.x;
    __shared__ float w[H * G];
    __shared__ float bb[H];
    if (threadIdx.x < H * G) w[threadIdx.x] = W0[t * H * G + threadIdx.x];
    if (threadIdx.x < H)     bb[threadIdx.x] = b0[t * H + threadIdx.x];
    __syncthreads();

    float accv[H];
#pragma unroll
    for (int h = 0; h < H; h++) accv[h] = bb[h];
#pragma unroll
    for (int gi = 0; gi < G; gi++) {
        const float v = g_dgT[(size_t)(t * G + gi) * B_DIM + b];
#pragma unroll
        for (int h = 0; h < H; h++) accv[h] += v * w[h * G + gi];
    }
#pragma unroll
    for (int h = 0; h < H; h++)
        g_z0[(size_t)(t * H + h) * B_DIM + b] = tanhf(accv[h]);
}

__device__ __forceinline__ void bn_stats_body(const float* __restrict__ x,
                                              float* __restrict__ mean,
                                              float* __restrict__ rstd)
{
    const int c = blockIdx.x;
    const float* p = x + (size_t)c * B_DIM;
    float s = 0.f, q = 0.f;
    for (int i = threadIdx.x; i < B_DIM; i += 256) {
        const float v = p[i];
        s += v; q += v * v;
    }
    __shared__ float sh_s[8], sh_q[8];
#pragma unroll
    for (int o = 16; o > 0; o >>= 1) {
        s += __shfl_down_sync(0xffffffffu, s, o);
        q += __shfl_down_sync(0xffffffffu, q, o);
    }
    const int w = threadIdx.x >> 5, l = threadIdx.x & 31;
    if (l == 0) { sh_s[w] = s; sh_q[w] = q; }
    __syncthreads();
    if (threadIdx.x == 0) {
        float S = 0.f, Q = 0.f;
#pragma unroll
        for (int i = 0; i < 8; i++) { S += sh_s[i]; Q += sh_q[i]; }
        const float m = S / (float)B_DIM;
        const float var = Q / (float)B_DIM - m * m;
        mean[c] = m;
        rstd[c] = rsqrtf(var + 1e-5f);
    }
}
__global__ __launch_bounds__(256) void bn_stats0_kernel() { bn_stats_body(g_z0, g_mean0, g_rstd0); }
__global__ __launch_bounds__(256) void bn_stats1_kernel() { bn_stats_body(g_z1, g_mean1, g_rstd1); }
__global__ __launch_bounds__(256) void bn_stats2_kernel() { bn_stats_body(g_z2, g_mean2, g_rstd2); }

__global__ __launch_bounds__(256) void apply0_kernel(
    const float* __restrict__ gam, const float* __restrict__ bet,
    const float* __restrict__ aw,  const float* __restrict__ ab,
    const float* __restrict__ av,  const float* __restrict__ ac,
    float* __restrict__ out)
{
    const int t = blockIdx.x;
    const int b = blockIdx.y * 256 + threadIdx.x;
    float s = 0.f;
#pragma unroll
    for (int h = 0; h < H; h++) {
        const int c = t * H + h;
        const float z = g_z0[(size_t)c * B_DIM + b];
        const float n = gam[c] * (z - g_mean0[c]) * g_rstd0[c] + bet[c];
        g_n0[(size_t)c * B_DIM + b] = n;
        out[(size_t)b * OUT_COLS + 551 + c] = n;
        s += n * aw[c];
    }
    out[(size_t)b * OUT_COLS + t] = tanhf(s + ab[t]) * av[t] + ac[t];
}

__global__ __launch_bounds__(256) void layer1_kernel(const float* __restrict__ W1,
                                                     const float* __restrict__ b1)
{
    const int t = blockIdx.x;
    const int b = blockIdx.y * 256 + threadIdx.x;
    __shared__ float w[H * 90];
    __shared__ float bb[H];
    for (int i = threadIdx.x; i < H * 90; i += 256) w[i] = W1[t * H * 90 + i];
    if (threadIdx.x < H) bb[threadIdx.x] = b1[t * H + threadIdx.x];
    __syncthreads();

    float accv[H];
#pragma unroll
    for (int h = 0; h < H; h++) accv[h] = bb[h];
#pragma unroll
    for (int j = 0; j < 60; j++) {
        const float v = g_n0[(size_t)(t * 60 + j) * B_DIM + b];
#pragma unroll
        for (int h = 0; h < H; h++) accv[h] += v * w[h * 90 + j];
    }
#pragma unroll
    for (int gi = 0; gi < G; gi++) {
        const float v = g_dgT[(size_t)((T0 + t) * G + gi) * B_DIM + b];
#pragma unroll
        for (int h = 0; h < H; h++) accv[h] += v * w[h * 90 + 60 + gi];
    }
#pragma unroll
    for (int h = 0; h < H; h++)
        g_z1[(size_t)(t * H + h) * B_DIM + b] = tanhf(accv[h]);
}

__global__ __launch_bounds__(256) void apply1_kernel(
    const float* __restrict__ gam, const float* __restrict__ bet,
    const float* __restrict__ aw,  const float* __restrict__ ab,
    const float* __restrict__ av,  const float* __restrict__ ac,
    float* __restrict__ out)
{
    const int t = blockIdx.x;
    const int b = blockIdx.y * 256 + threadIdx.x;
    float s = 0.f;
#pragma unroll
    for (int h = 0; h < H; h++) {
        const int c = t * H + h;
        const float z = g_z1[(size_t)c * B_DIM + b];
        const float n = gam[c] * (z - g_mean1[c]) * g_rstd1[c] + bet[c];
        g_n1[(size_t)c * B_DIM + b] = n;
        out[(size_t)b * OUT_COLS + 551 + 3000 + c] = n;
        s += n * aw[c];
    }
    out[(size_t)b * OUT_COLS + T0 + t] = tanhf(s + ab[t]) * av[t] + ac[t];
}

__global__ __launch_bounds__(256) void root_kernel(const float* __restrict__ W2,
                                                   const float* __restrict__ b2)
{
    const int b = blockIdx.x * 256 + threadIdx.x;
    __shared__ float w[H * 330];
    __shared__ float bb[H];
    for (int i = threadIdx.x; i < H * 330; i += 256) w[i] = W2[i];
    if (threadIdx.x < H) bb[threadIdx.x] = b2[threadIdx.x];
    __syncthreads();

    float accv[H];
#pragma unroll
    for (int h = 0; h < H; h++) accv[h] = bb[h];
    for (int c = 0; c < 300; c++) {
        const float v = g_n1[(size_t)c * B_DIM + b];
#pragma unroll
        for (int h = 0; h < H; h++) accv[h] += v * w[h * 330 + c];
    }
#pragma unroll
    for (int gi = 0; gi < G; gi++) {
        const float v = g_dgT[(size_t)(550 * G + gi) * B_DIM + b];
#pragma unroll
        for (int h = 0; h < H; h++) accv[h] += v * w[h * 330 + 300 + gi];
    }
#pragma unroll
    for (int h = 0; h < H; h++)
        g_z2[(size_t)h * B_DIM + b] = tanhf(accv[h]);
}

__global__ __launch_bounds__(256) void apply2_kernel(
    const float* __restrict__ gam, const float* __restrict__ bet,
    const float* __restrict__ aw,  const float* __restrict__ ab,
    const float* __restrict__ av,  const float* __restrict__ ac,
    float* __restrict__ out)
{
    const int b = blockIdx.x * 256 + threadIdx.x;
    float s = 0.f;
#pragma unroll
    for (int h = 0; h < H; h++) {
        const float z = g_z2[(size_t)h * B_DIM + b];
        const float n = gam[h] * (z - g_mean2[h]) * g_rstd2[h] + bet[h];
        out[(size_t)b * OUT_COLS + 551 + 3300 + h] = n;
        s += n * aw[h];
    }
    out[(size_t)b * OUT_COLS + 550] = tanhf(s + ab[0]) * av[0] + ac[0];
}

// =====================================================================
// launch
// =====================================================================
extern "C" void kernel_launch(void* const* d_in, const int* in_sizes, int n_in,
                              void* d_out, int out_size)
{
    const float* cell = (const float*)d_in[0];
    const float* Wdg  = (const float*)d_in[1];
    const float* bdg  = (const float*)d_in[2];
    const float* W0   = (const float*)d_in[3];
    const float* b0   = (const float*)d_in[4];
    const float* gam0 = (const float*)d_in[5];
    const float* bet0 = (const float*)d_in[6];
    const float* aw0  = (const float*)d_in[7];
    const float* ab0  = (const float*)d_in[8];
    const float* av0  = (const float*)d_in[9];
    const float* ac0  = (const float*)d_in[10];
    const float* W1   = (const float*)d_in[11];
    const float* b1   = (const float*)d_in[12];
    const float* gam1 = (const float*)d_in[13];
    const float* bet1 = (const float*)d_in[14];
    const float* aw1  = (const float*)d_in[15];
    const float* ab1  = (const float*)d_in[16];
    const float* av1  = (const float*)d_in[17];
    const float* ac1  = (const float*)d_in[18];
    const float* W2   = (const float*)d_in[19];
    const float* b2   = (const float*)d_in[20];
    const float* gam2 = (const float*)d_in[21];
    const float* bet2 = (const float*)d_in[22];
    const float* aw2  = (const float*)d_in[23];
    const float* ab2  = (const float*)d_in[24];
    const float* av2  = (const float*)d_in[25];
    const float* ac2  = (const float*)d_in[26];
    float* out = (float*)d_out;

    // resolve device-global scratch addresses for the conversion kernels
    __half* dAh = nullptr;
    __half* dWh = nullptr;
    cudaGetSymbolAddress((void**)&dAh, g_Ah);
    cudaGetSymbolAddress((void**)&dWh, g_Wh);

    // fp32 -> fp16 pre-conversion (once per launch; graph-capturable)
    const size_t nA4 = (size_t)B_DIM * NG / 4;       // 3,072,000
    const size_t nW4 = (size_t)N_DG * NG / 4;        // 12,397,500
    conv_h_kernel<<<(unsigned)((nA4 + 255) / 256), 256>>>(cell, dAh, nA4);
    conv_h_kernel<<<(unsigned)((nW4 + 255) / 256), 256>>>(Wdg, dWh, nW4);

    // GEMM: x = n-tile (130), y = m-tile (32) — validated order
    dim3 gemm_grid((N_DG + 127) / 128, B_DIM / 128);
    gemm_dg_kernel<<<gemm_grid, 256>>>(dAh, dWh, bdg);

    layer0_kernel<<<dim3(T0, B_DIM / 256), 256>>>(W0, b0);
    bn_stats0_kernel<<<T0 * H, 256>>>();
    apply0_kernel<<<dim3(T0, B_DIM / 256), 256>>>(gam0, bet0, aw0, ab0, av0, ac0, out);

    layer1_kernel<<<dim3(T1, B_DIM / 256), 256>>>(W1, b1);
    bn_stats1_kernel<<<T1 * H, 256>>>();
    apply1_kernel<<<dim3(T1, B_DIM / 256), 256>>>(gam1, bet1, aw1, ab1, av1, ac1, out);

    root_kernel<<<B_DIM / 256, 256>>>(W2, b2);
    bn_stats2_kernel<<<H, 256>>>();
    apply2_kernel<<<B_DIM / 256, 256>>>(gam2, bet2, aw2, ab2, av2, ac2, out);
}